// round 16
// baseline (speedup 1.0000x reference)
#include <cuda_runtime.h>
#include <cstdint>

#define E_DIM 128
#define B_SZ  1024
#define T_SZ  200
#define GRID  296
#define NTHR  256

#define ROW_A 272            // 128 fp16 padded to 272B (ldmatrix conflict-free)

#define OFF_A    0           // 208*272 = 56576
#define OFF_STG  56576       // 2 x 25600 fp32 staging (50 rows each)
#define STG_SZ   25600
#define OFF_RED  107776      // 416 f32 (also sq/sr overlay during prologue)
#define OFF_QAO  109440      // 4*64 f32 own-batch qA
#define SMEM_BYTES 110464    // x2 CTAs/SM = 220928

// device scratch
__device__ float g_WkF[8192];           // fragment-ordered W0b-W0c
__device__ float g_WdF[8192];           // fragment-ordered W0d
__device__ float g_WqT[128 * 64];       // [e*64+h] W0a+W0c
__device__ uint4 g_Wbf[B_SZ * 1024];    // per-batch B fragments (built+read by owning CTA)
__device__ unsigned int g_barA, g_barB; // grid barrier (self-resetting)

__device__ __forceinline__ uint32_t pkf16(float lo, float hi) {
    uint32_t r;
    asm("cvt.rn.f16x2.f32 %0, %1, %2;" : "=r"(r) : "f"(hi), "f"(lo));
    return r;
}
__device__ __forceinline__ uint32_t smem_u32(const void* p) {
    uint32_t a;
    asm("{ .reg .u64 t; cvta.to.shared.u64 t, %1; cvt.u32.u64 %0, t; }" : "=r"(a) : "l"(p));
    return a;
}
__device__ __forceinline__ void cp16(uint32_t dst, const float4* src) {
    asm volatile("cp.async.cg.shared.global [%0], [%1], 16;"
                 :: "r"(dst), "l"(__cvta_generic_to_global(src)) : "memory");
}
#define CP_COMMIT() asm volatile("cp.async.commit_group;" ::: "memory")
#define CP_WAIT(n)  asm volatile("cp.async.wait_group %0;" :: "n"(n) : "memory")

#define LDSM4(r, addr) \
    asm volatile("ldmatrix.sync.aligned.m8n8.x4.shared.b16 {%0,%1,%2,%3}, [%4];" \
        : "=r"((r)[0]), "=r"((r)[1]), "=r"((r)[2]), "=r"((r)[3]) : "r"(addr))

__device__ __forceinline__ void mma_f16(float* c, const uint32_t* a, uint32_t b0, uint32_t b1) {
    asm volatile("mma.sync.aligned.m16n8k16.row.col.f32.f16.f16.f32 "
        "{%0,%1,%2,%3}, {%4,%5,%6,%7}, {%8,%9}, {%0,%1,%2,%3};"
        : "+f"(c[0]), "+f"(c[1]), "+f"(c[2]), "+f"(c[3])
        : "r"(a[0]), "r"(a[1]), "r"(a[2]), "r"(a[3]), "r"(b0), "r"(b1));
}

__global__ void __launch_bounds__(NTHR, 2) lau_main(
    const float* __restrict__ keys, const float* __restrict__ query,
    const float* __restrict__ W0,   const float* __restrict__ b0,
    const float* __restrict__ W1,   const float* __restrict__ b1,
    float* __restrict__ out)
{
    extern __shared__ __align__(1024) char sm[];
    const uint32_t smb = smem_u32(sm);
    const int tid = threadIdx.x;
    const int bid = blockIdx.x;
    const int w = tid >> 5, lane = tid & 31;
    const int mg = w >> 1, ng = w & 1;          // 4 m-groups x 2 n-groups
    const int lq = lane >> 2, lr = lane & 3;
    float* sRed = (float*)(sm + OFF_RED);
    float* sQao = (float*)(sm + OFF_QAO);

    const int nb = (B_SZ - 1 - bid) / GRID + 1;
    const int nchunks = 4 * nb;

    // ---- epilogue constants, zero A tail ----
    float w1v[8];
    #pragma unroll
    for (int nt = 0; nt < 4; nt++) {
        w1v[2 * nt]     = __ldg(&W1[ng * 32 + nt * 8 + 2 * lr]);
        w1v[2 * nt + 1] = __ldg(&W1[ng * 32 + nt * 8 + 2 * lr + 1]);
    }
    const float b1v = __ldg(b1);
    if (tid < 136)
        *(uint4*)(sm + OFF_A + 200 * ROW_A + tid * 16) = make_uint4(0, 0, 0, 0);

    // ---- kick chunks 0,1 of first batch (overlaps all prep below) ----
    #pragma unroll
    for (int s = 0; s < 2; s++) {
        const float4* src = (const float4*)(keys + ((size_t)bid * T_SZ + s * 50) * E_DIM);
        uint32_t stg = smb + OFF_STG + (s & 1) * STG_SZ;
        #pragma unroll
        for (int i = 0; i < 7; i++) {
            int idx = i * NTHR + tid;
            if (idx < 1600) cp16(stg + idx * 16, src + idx);
        }
        CP_COMMIT();
    }

    // ---- fold phase: W0 -> fragment tables (spread over grid, <=1 item/thread) ----
    {
        int gtid = bid * NTHR + tid;
        if (gtid < 8192) {
            int id = gtid >> 3, u = gtid & 7;
            int ln = id & 31, k2 = (id >> 5) & 3, nt = (id >> 7) & 3, g = id >> 9;
            int h = g * 32 + nt * 8 + (ln >> 2);
            int e = 32 * k2 + 2 * (ln & 3) + ((u >> 1) << 3) + (u & 1);
            g_WkF[gtid] = __ldg(&W0[(128 + e) * 64 + h]) - __ldg(&W0[(256 + e) * 64 + h]);
            g_WdF[gtid] = __ldg(&W0[(384 + e) * 64 + h]);
        } else if (gtid < 16384) {
            int i = gtid - 8192;
            int h = i & 63, e = i >> 6;
            g_WqT[e * 64 + h] = __ldg(&W0[e * 64 + h]) + __ldg(&W0[(256 + e) * 64 + h]);
        }
        __threadfence();
    }
    __syncthreads();

    // ---- grid barrier (all 296 CTAs co-resident; self-resetting for graph replays) ----
    if (tid == 0) {
        atomicAdd(&g_barA, 1u);
        while (*(volatile unsigned int*)&g_barA < GRID) { __nanosleep(32); }
        __threadfence();
        unsigned int t2 = atomicAdd(&g_barB, 1u);
        if (t2 == GRID - 1u) {
            *(volatile unsigned int*)&g_barA = 0u;
            *(volatile unsigned int*)&g_barB = 0u;
            __threadfence();
        }
    }
    __syncthreads();

    // ---- own-batch prep: B fragments -> g_Wbf, qA -> smem ----
    {
        float* sq = sRed;              // 128 f (overlay; staging area is NOT touched)
        float* sr = sRed + 128;        // 256 f
        for (int j = 0; j < nb; j++) {
            const int b = bid + j * GRID;
            if (tid < 128) sq[tid] = __ldg(&query[(size_t)b * E_DIM + tid]);
            __syncthreads();
            #pragma unroll
            for (int jj = 0; jj < 4; jj++) {
                int id = jj * 256 + tid;
                int ln = id & 31, k2 = (id >> 5) & 3;
                int e0 = 32 * k2 + 2 * (ln & 3);
                float4 wk0 = __ldg((const float4*)(g_WkF + id * 8));
                float4 wk1 = __ldg((const float4*)(g_WkF + id * 8 + 4));
                float4 wd0 = __ldg((const float4*)(g_WdF + id * 8));
                float4 wd1 = __ldg((const float4*)(g_WdF + id * 8 + 4));
                uint4 v;
                v.x = pkf16(fmaf(sq[e0],      wd0.x, wk0.x), fmaf(sq[e0 + 1],  wd0.y, wk0.y));
                v.y = pkf16(fmaf(sq[e0 + 8],  wd0.z, wk0.z), fmaf(sq[e0 + 9],  wd0.w, wk0.w));
                v.z = pkf16(fmaf(sq[e0 + 16], wd1.x, wk1.x), fmaf(sq[e0 + 17], wd1.y, wk1.y));
                v.w = pkf16(fmaf(sq[e0 + 24], wd1.z, wk1.z), fmaf(sq[e0 + 25], wd1.w, wk1.w));
                g_Wbf[(size_t)b * 1024 + id] = v;
            }
            {
                int h6 = tid & 63, grp = tid >> 6;
                float p = 0.f;
                #pragma unroll 8
                for (int i = 0; i < 32; i++) {
                    int e = grp * 32 + i;
                    p += sq[e] * __ldg(&g_WqT[e * 64 + h6]);
                }
                sr[grp * 64 + h6] = p;
            }
            __syncthreads();
            if (tid < 64)
                sQao[j * 64 + tid] = __ldg(&b0[tid]) + sr[tid] + sr[64 + tid]
                                   + sr[128 + tid] + sr[192 + tid];
            __syncthreads();
        }
    }

    const uint32_t aB = smb + OFF_A + (lane & 15) * ROW_A + (lane >> 4) * 16;

    // ================= main loop (R14-verified) =================
    int j = 0;
    for (int b = bid; b < B_SZ; b += GRID, j++) {
        // B fragments (coalesced, L2-hot: written by this CTA above)
        uint32_t bf[4][8][2];
        {
            const uint4* wb4 = g_Wbf + ((size_t)b * 2 + ng) * 512 + lane;
            #pragma unroll
            for (int nt = 0; nt < 4; nt++)
                #pragma unroll
                for (int k2 = 0; k2 < 4; k2++) {
                    uint4 v = __ldg(&wb4[nt * 128 + k2 * 32]);
                    bf[nt][2 * k2][0] = v.x;     bf[nt][2 * k2][1] = v.y;
                    bf[nt][2 * k2 + 1][0] = v.z; bf[nt][2 * k2 + 1][1] = v.w;
                }
        }
        float qa[8];
        #pragma unroll
        for (int nt = 0; nt < 4; nt++) {
            qa[2 * nt]     = sQao[j * 64 + ng * 32 + nt * 8 + 2 * lr];
            qa[2 * nt + 1] = sQao[j * 64 + ng * 32 + nt * 8 + 2 * lr + 1];
        }

        // ---- 4 convert phases (self-mapped; cross-batch refill) ----
        #pragma unroll
        for (int c = 0; c < 4; c++) {
            const int s = 4 * j + c;
            CP_WAIT(1);
            const float4* s4 = (const float4*)(sm + OFF_STG + (s & 1) * STG_SZ);
            float4 v[7];
            #pragma unroll
            for (int i = 0; i < 7; i++) {
                int idx = i * NTHR + tid;
                if (idx < 1600) v[i] = s4[idx];
            }
            const int s2 = s + 2;
            if (s2 < nchunks) {
                int b2 = bid + (s2 >> 2) * GRID;
                const float4* src = (const float4*)(keys + ((size_t)b2 * T_SZ + (s2 & 3) * 50) * E_DIM);
                uint32_t stg = smb + OFF_STG + (s2 & 1) * STG_SZ;
                #pragma unroll
                for (int i = 0; i < 7; i++) {
                    int idx = i * NTHR + tid;
                    if (idx < 1600) cp16(stg + idx * 16, src + idx);
                }
            }
            CP_COMMIT();
            #pragma unroll
            for (int i = 0; i < 7; i++) {
                int idx = i * NTHR + tid;
                if (idx < 1600) {
                    int row = c * 50 + (idx >> 5), cc = idx & 31;
                    *(uint2*)(sm + OFF_A + row * ROW_A + cc * 8) =
                        make_uint2(pkf16(v[i].x, v[i].y), pkf16(v[i].z, v[i].w));
                }
            }
        }
        __syncthreads();                         // (S1) A ready

        // ---- per-tile mma + inline epilogue ----
        #pragma unroll
        for (int i = 0; i < 4; i++) {
            int t = mg + 4 * i;
            if (t < 13) {
                float acc[4][4];
                #pragma unroll
                for (int nt = 0; nt < 4; nt++)
                    #pragma unroll
                    for (int u = 0; u < 4; u++) acc[nt][u] = 0.f;
                #pragma unroll
                for (int ks = 0; ks < 8; ks++) {
                    uint32_t a[4];
                    LDSM4(a, aB + t * (16 * ROW_A) + ks * 32);
                    #pragma unroll
                    for (int nt = 0; nt < 4; nt++)
                        mma_f16(acc[nt], a, bf[nt][ks][0], bf[nt][ks][1]);
                }
                float p0 = 0.f, p1 = 0.f;
                #pragma unroll
                for (int nt = 0; nt < 4; nt++) {
                    p0 += fmaxf(acc[nt][0] + qa[2 * nt],     0.f) * w1v[2 * nt]
                        + fmaxf(acc[nt][1] + qa[2 * nt + 1], 0.f) * w1v[2 * nt + 1];
                    p1 += fmaxf(acc[nt][2] + qa[2 * nt],     0.f) * w1v[2 * nt]
                        + fmaxf(acc[nt][3] + qa[2 * nt + 1], 0.f) * w1v[2 * nt + 1];
                }
                p0 += __shfl_xor_sync(0xffffffffu, p0, 1);
                p0 += __shfl_xor_sync(0xffffffffu, p0, 2);
                p1 += __shfl_xor_sync(0xffffffffu, p1, 1);
                p1 += __shfl_xor_sync(0xffffffffu, p1, 2);
                if (lr == 0) {
                    sRed[ng * 208 + t * 16 + lq]     = p0;
                    sRed[ng * 208 + t * 16 + lq + 8] = p1;
                }
            }
        }
        __syncthreads();                         // (S2) sRed ready
        if (tid < T_SZ)
            out[(size_t)b * T_SZ + tid] = sRed[tid] + sRed[208 + tid] + b1v;
        // next batch's S1 orders A/sRed reuse
    }
}

extern "C" void kernel_launch(void* const* d_in, const int* in_sizes, int n_in,
                              void* d_out, int out_size) {
    const float* query = (const float*)d_in[0];
    const float* keys  = (const float*)d_in[1];
    const float* W0    = (const float*)d_in[2];
    const float* b0    = (const float*)d_in[3];
    const float* W1    = (const float*)d_in[4];
    const float* b1    = (const float*)d_in[5];
    float* out = (float*)d_out;

    cudaFuncSetAttribute(lau_main, cudaFuncAttributeMaxDynamicSharedMemorySize, SMEM_BYTES);
    lau_main<<<GRID, NTHR, SMEM_BYTES>>>(keys, query, W0, b0, W1, b1, out);
}